// round 7
// baseline (speedup 1.0000x reference)
#include <cuda_runtime.h>
#include <cuda_bf16.h>
#include <cstdint>

// MoChA monotonic attention: B=16, KMAX=4096, DK=DQ=DV=A=512
// out[0:8192] = cv [16,1,512] ; out[8192:73728] = aw [16,4096,1]

#define DINL __device__ __forceinline__
#define NROWS 65536            // B*KMAX
#define KS_STRIDE 520          // key smem row stride (bf16), pad 8 -> conflict-free frag LDS
#define WS_STRIDE 72           // wk smem row stride (bf16)

// ---- device scratch (no allocations allowed) ----
__device__ __nv_bfloat16 g_wk_bf16[512 * 512];
__device__ float g_qb[16 * 512];
__device__ float g_vw[512];
__device__ float g_emono[NROWS];
__device__ float g_aw[NROWS];
__device__ float g_cvpart[16 * 16 * 512];

// smem layout for gemm kernel (dynamic)
#define OFF_WK   133120u                    // key_s: 128*520*2 = 133120
#define OFF_QB   (OFF_WK + 18432u)          // wk_s: 128*72*2 = 18432
#define OFF_VW   (OFF_QB + 2048u)
#define OFF_ERED (OFF_VW + 2048u)
#define SMEM_GEMM (OFF_ERED + 1024u)        // 156672 B

DINL float tanh_fast(float x) {
    float y;
    asm("tanh.approx.f32 %0, %1;" : "=f"(y) : "f"(x));
    return y;
}

// ============================================================
// prep: wk fp32->bf16; qb[b][a] = query[b]·wq_w[a] + wk_b[a]; vw = weight-norm
// grid 2049 x 256
// ============================================================
__global__ void prep_kernel(const float* __restrict__ wk_w,
                            const float* __restrict__ query,
                            const float* __restrict__ wq_w,
                            const float* __restrict__ wk_b,
                            const float* __restrict__ v_v,
                            const float* __restrict__ v_g) {
    int blk = blockIdx.x;
    if (blk < 1024) {
        int e = blk * 256 + threadIdx.x;
        g_wk_bf16[e] = __float2bfloat16(wk_w[e]);
    } else if (blk < 2048) {
        int wid = threadIdx.x >> 5, lane = threadIdx.x & 31;
        int idx = (blk - 1024) * 8 + wid;      // 0..8191 = b*512+a
        int b = idx >> 9, a = idx & 511;
        const float* qrow = query + b * 512;
        const float* wrow = wq_w + (size_t)a * 512;
        float s = 0.f;
        #pragma unroll
        for (int i = 0; i < 16; i++) {
            int d = lane + i * 32;
            s += qrow[d] * wrow[d];
        }
        #pragma unroll
        for (int o = 16; o > 0; o >>= 1) s += __shfl_down_sync(0xffffffffu, s, o);
        if (lane == 0) g_qb[idx] = s + wk_b[a];
    } else {
        __shared__ float red[256];
        int t = threadIdx.x;
        float a0 = v_v[t], a1 = v_v[t + 256];
        red[t] = a0 * a0 + a1 * a1;
        __syncthreads();
        for (int o = 128; o > 0; o >>= 1) {
            if (t < o) red[t] += red[t + o];
            __syncthreads();
        }
        float inv = v_g[0] * rsqrtf(red[0]);
        g_vw[t]       = v_v[t] * inv;
        g_vw[t + 256] = v_v[t + 256] * inv;
    }
}

// ============================================================
// fused GEMM + tanh reduce -> e_mono
// grid 512 CTAs x 256 threads; CTA = 128 rows x (A=512 via 4 chunks of 128)
// warp grid 4(row) x 2(col); warp tile 32 x 64; mma.sync m16n8k16 bf16
// ============================================================
__global__ void __launch_bounds__(256, 1)
gemm_kernel(const float* __restrict__ key, const float* __restrict__ rv) {
    extern __shared__ char smem[];
    __nv_bfloat16* key_s = (__nv_bfloat16*)smem;
    __nv_bfloat16* wk_s  = (__nv_bfloat16*)(smem + OFF_WK);
    float* qb_s  = (float*)(smem + OFF_QB);
    float* vw_s  = (float*)(smem + OFF_VW);
    float* e_red = (float*)(smem + OFF_ERED);

    int tid = threadIdx.x;
    int wid = tid >> 5, lane = tid & 31;
    int wr = wid >> 1, wc = wid & 1;        // warp row 0..3, warp col 0..1
    int gp = lane >> 2, tq = lane & 3;      // mma groupID, quad id

    int b = blockIdx.x >> 5;                // 32 tiles of 128 rows per batch
    size_t row0 = (size_t)blockIdx.x * 128;

    for (int i = tid; i < 512; i += 256) {
        qb_s[i] = g_qb[b * 512 + i];
        vw_s[i] = g_vw[i];
    }

    // stage key tile [128 x 512] fp32 -> bf16 smem (padded stride)
    const float* kg = key + row0 * 512;
    for (int e = tid * 4; e < 65536; e += 1024) {
        int r = e >> 9, c = e & 511;
        float4 v = *(const float4*)(kg + (size_t)r * 512 + c);
        uint32_t p0, p1;
        asm("cvt.rn.bf16x2.f32 %0, %1, %2;" : "=r"(p0) : "f"(v.y), "f"(v.x));
        asm("cvt.rn.bf16x2.f32 %0, %1, %2;" : "=r"(p1) : "f"(v.w), "f"(v.z));
        uint2 pk; pk.x = p0; pk.y = p1;
        *(uint2*)(key_s + r * KS_STRIDE + c) = pk;
    }
    __syncthreads();

    float erow[4] = {0.f, 0.f, 0.f, 0.f};   // rows wr*32 + {gp, gp+8, gp+16, gp+24}

    #pragma unroll 1
    for (int ac = 0; ac < 4; ac++) {        // a-chunk of 128 cols
        float acc[2][8][4];
        #pragma unroll
        for (int mt = 0; mt < 2; mt++)
            #pragma unroll
            for (int nt = 0; nt < 8; nt++)
                #pragma unroll
                for (int f = 0; f < 4; f++) acc[mt][nt][f] = 0.f;

        #pragma unroll 1
        for (int kc = 0; kc < 8; kc++) {    // K chunk of 64
            __syncthreads();
            // load wk tile [128 x 64] bf16 from global
            #pragma unroll
            for (int it = 0; it < 4; it++) {
                int e = tid * 8 + it * 2048;
                int rr = e >> 6, cc = e & 63;
                uint4 v = *(const uint4*)(g_wk_bf16 +
                    (size_t)(ac * 128 + rr) * 512 + kc * 64 + cc);
                *(uint4*)(wk_s + rr * WS_STRIDE + cc) = v;
            }
            __syncthreads();

            #pragma unroll
            for (int ks = 0; ks < 4; ks++) {  // k-steps of 16
                int kof = kc * 64 + ks * 16;
                uint32_t afr[2][4];
                #pragma unroll
                for (int mt = 0; mt < 2; mt++) {
                    const __nv_bfloat16* ap = key_s +
                        (wr * 32 + mt * 16 + gp) * KS_STRIDE + kof + tq * 2;
                    afr[mt][0] = *(const uint32_t*)(ap);
                    afr[mt][1] = *(const uint32_t*)(ap + 8 * KS_STRIDE);
                    afr[mt][2] = *(const uint32_t*)(ap + 8);
                    afr[mt][3] = *(const uint32_t*)(ap + 8 * KS_STRIDE + 8);
                }
                uint32_t bfr[8][2];
                #pragma unroll
                for (int nt = 0; nt < 8; nt++) {
                    const __nv_bfloat16* bp = wk_s +
                        (wc * 64 + nt * 8 + gp) * WS_STRIDE + ks * 16 + tq * 2;
                    bfr[nt][0] = *(const uint32_t*)(bp);
                    bfr[nt][1] = *(const uint32_t*)(bp + 8);
                }
                #pragma unroll
                for (int mt = 0; mt < 2; mt++)
                    #pragma unroll
                    for (int nt = 0; nt < 8; nt++) {
                        asm volatile(
                            "mma.sync.aligned.m16n8k16.row.col.f32.bf16.bf16.f32 "
                            "{%0,%1,%2,%3}, {%4,%5,%6,%7}, {%8,%9}, {%0,%1,%2,%3};"
                            : "+f"(acc[mt][nt][0]), "+f"(acc[mt][nt][1]),
                              "+f"(acc[mt][nt][2]), "+f"(acc[mt][nt][3])
                            : "r"(afr[mt][0]), "r"(afr[mt][1]),
                              "r"(afr[mt][2]), "r"(afr[mt][3]),
                              "r"(bfr[nt][0]), "r"(bfr[nt][1]));
                    }
            }
        }

        // epilogue: tanh(c + qb) * vw, accumulate per-row
        #pragma unroll
        for (int mt = 0; mt < 2; mt++)
            #pragma unroll
            for (int nt = 0; nt < 8; nt++) {
                int col = ac * 128 + wc * 64 + nt * 8 + tq * 2;
                float q0 = qb_s[col], q1 = qb_s[col + 1];
                float w0 = vw_s[col], w1 = vw_s[col + 1];
                erow[mt * 2 + 0] += tanh_fast(acc[mt][nt][0] + q0) * w0
                                  + tanh_fast(acc[mt][nt][1] + q1) * w1;
                erow[mt * 2 + 1] += tanh_fast(acc[mt][nt][2] + q0) * w0
                                  + tanh_fast(acc[mt][nt][3] + q1) * w1;
            }
    }

    // reduce across the 4 lanes sharing each row (same groupID)
    #pragma unroll
    for (int i = 0; i < 4; i++) {
        erow[i] += __shfl_xor_sync(0xffffffffu, erow[i], 1);
        erow[i] += __shfl_xor_sync(0xffffffffu, erow[i], 2);
    }
    if (tq == 0) {
        int base = wc * 128 + wr * 32 + gp;
        e_red[base]      = erow[0];
        e_red[base + 8]  = erow[1];
        e_red[base + 16] = erow[2];
        e_red[base + 24] = erow[3];
    }
    __syncthreads();
    if (tid < 128)
        g_emono[row0 + tid] = e_red[tid] + e_red[128 + tid] + rv[0];
}

// ============================================================
// scan: aw[i] = p[i] * exp(1 + sum_{j<i} log(1-p[j])) ; per-batch block scan
// grid 16 x 1024 (4 elems/thread)
// ============================================================
__global__ void __launch_bounds__(1024)
scan_kernel(const float* __restrict__ noise, float* __restrict__ out) {
    __shared__ float wsum[32];
    int b = blockIdx.x, t = threadIdx.x;
    float p[4], l[4];
    float local = 0.f;
    #pragma unroll
    for (int i = 0; i < 4; i++) {
        int k = t * 4 + i;
        float e = g_emono[b * 4096 + k] + noise[b * 4096 + k];
        float pp = 1.f / (1.f + expf(-e));
        p[i] = pp;
        l[i] = logf(fmaxf(1.f - pp, 1e-10f));
        local += l[i];
    }
    float s = local;
    #pragma unroll
    for (int o = 1; o < 32; o <<= 1) {
        float v = __shfl_up_sync(0xffffffffu, s, o);
        if ((t & 31) >= o) s += v;
    }
    if ((t & 31) == 31) wsum[t >> 5] = s;
    __syncthreads();
    if (t < 32) {
        float v = wsum[t];
        #pragma unroll
        for (int o = 1; o < 32; o <<= 1) {
            float u = __shfl_up_sync(0xffffffffu, v, o);
            if (t >= o) v += u;
        }
        wsum[t] = v;
    }
    __syncthreads();
    float run = s - local;                    // exclusive prefix within warp
    if (t >= 32) run += wsum[(t >> 5) - 1];
    #pragma unroll
    for (int i = 0; i < 4; i++) {
        int k = t * 4 + i;
        float aw = p[i] * expf(1.f + run);
        g_aw[b * 4096 + k] = aw;
        out[8192 + b * 4096 + k] = aw;
        run += l[i];
    }
}

// ============================================================
// cv split-K partials: grid 256 = (b)*16 + split ; each: 256 k-rows x 512 v
// ============================================================
__global__ void __launch_bounds__(256)
cvpart_kernel(const float* __restrict__ value) {
    __shared__ float aw_s[256];
    int b = blockIdx.x >> 4, s = blockIdx.x & 15;
    int t = threadIdx.x;
    int k0 = s * 256;
    aw_s[t] = g_aw[b * 4096 + k0 + t];
    __syncthreads();
    const float* vb = value + ((size_t)b * 4096 + k0) * 512;
    float a0 = 0.f, a1 = 0.f;
    #pragma unroll 4
    for (int k = 0; k < 256; k++) {
        float w = aw_s[k];
        a0 += w * vb[(size_t)k * 512 + t];
        a1 += w * vb[(size_t)k * 512 + t + 256];
    }
    g_cvpart[(b * 16 + s) * 512 + t]       = a0;
    g_cvpart[(b * 16 + s) * 512 + t + 256] = a1;
}

// reduce partials -> cv : grid 32 x 256
__global__ void __launch_bounds__(256)
cvred_kernel(float* __restrict__ out) {
    int idx = blockIdx.x * 256 + threadIdx.x;   // 0..8191
    int b = idx >> 9, v = idx & 511;
    float s = 0.f;
    #pragma unroll
    for (int i = 0; i < 16; i++) s += g_cvpart[(b * 16 + i) * 512 + v];
    out[idx] = s;
}

// ============================================================
extern "C" void kernel_launch(void* const* d_in, const int* in_sizes, int n_in,
                              void* d_out, int out_size) {
    const float* key   = (const float*)d_in[0];
    const float* value = (const float*)d_in[1];
    const float* query = (const float*)d_in[2];
    const float* noise = (const float*)d_in[3];
    const float* wk_w  = (const float*)d_in[4];
    const float* wk_b  = (const float*)d_in[5];
    const float* wq_w  = (const float*)d_in[6];
    const float* v_v   = (const float*)d_in[7];
    const float* v_g   = (const float*)d_in[8];
    const float* r     = (const float*)d_in[9];
    float* out = (float*)d_out;

    cudaFuncSetAttribute(gemm_kernel,
        cudaFuncAttributeMaxDynamicSharedMemorySize, (int)SMEM_GEMM);

    prep_kernel<<<2049, 256>>>(wk_w, query, wq_w, wk_b, v_v, v_g);
    gemm_kernel<<<512, 256, SMEM_GEMM>>>(key, r);
    scan_kernel<<<16, 1024>>>(noise, out);
    cvpart_kernel<<<256, 256>>>(value);
    cvred_kernel<<<32, 256>>>(out);
}

// round 12
// speedup vs baseline: 1.0903x; 1.0903x over previous
#include <cuda_runtime.h>
#include <cuda_bf16.h>
#include <cstdint>

// MoChA: B=16, KMAX=4096, D=A=512. out[0:8192]=cv ; out[8192:73728]=aw
#define DINL __device__ __forceinline__
#define NROWS 65536
#define KS_STRIDE 520          // key smem row stride (bf16)
#define WS_STRIDE 72           // wk smem row stride (bf16)

__device__ __nv_bfloat16 g_wk_bf16[512 * 512];
__device__ float g_qb[16 * 512];
__device__ float g_vw[512];
__device__ float g_emono[NROWS];
__device__ float g_aw[NROWS];
__device__ float g_cvpart[16 * 64 * 512];   // 2 MB partials

// gemm smem: key_s [0,133120) ; wk double buf [133120, +2*18432) ; qv ; e_red
#define OFF_WKB  133120u
#define OFF_QV2  169984u
#define OFF_ERED 174080u
#define SMEM_GEMM 175104u

DINL uint32_t smem_u32(const void* p) {
    uint32_t a;
    asm("{ .reg .u64 t; cvta.to.shared.u64 t, %1; cvt.u32.u64 %0, t; }"
        : "=r"(a) : "l"(p));
    return a;
}
DINL float tanh_fast(float x) {
    float y; asm("tanh.approx.f32 %0, %1;" : "=f"(y) : "f"(x)); return y;
}
DINL void cp_async16(uint32_t dst, const void* src) {
    asm volatile("cp.async.cg.shared.global [%0], [%1], 16;"
                 :: "r"(dst), "l"(src) : "memory");
}
DINL void cp_commit() { asm volatile("cp.async.commit_group;" ::: "memory"); }
DINL void cp_wait0()  { asm volatile("cp.async.wait_group 0;" ::: "memory"); }
DINL void ldsm_x4(uint32_t a, uint32_t& r0, uint32_t& r1, uint32_t& r2, uint32_t& r3) {
    asm volatile("ldmatrix.sync.aligned.m8n8.x4.shared.b16 {%0,%1,%2,%3}, [%4];"
                 : "=r"(r0), "=r"(r1), "=r"(r2), "=r"(r3) : "r"(a));
}

// ============================================================
// prep: wk fp32->bf16; qb = query@wq^T + wk_b; vw = weight-norm
// ============================================================
__global__ void prep_kernel(const float* __restrict__ wk_w,
                            const float* __restrict__ query,
                            const float* __restrict__ wq_w,
                            const float* __restrict__ wk_b,
                            const float* __restrict__ v_v,
                            const float* __restrict__ v_g) {
    int blk = blockIdx.x;
    if (blk < 1024) {
        int e = blk * 256 + threadIdx.x;
        g_wk_bf16[e] = __float2bfloat16(wk_w[e]);
    } else if (blk < 2048) {
        int wid = threadIdx.x >> 5, lane = threadIdx.x & 31;
        int idx = (blk - 1024) * 8 + wid;   // b*512+a
        int b = idx >> 9, a = idx & 511;
        const float* qrow = query + b * 512;
        const float* wrow = wq_w + (size_t)a * 512;
        float s = 0.f;
        #pragma unroll
        for (int i = 0; i < 16; i++) s += qrow[lane + i * 32] * wrow[lane + i * 32];
        #pragma unroll
        for (int o = 16; o > 0; o >>= 1) s += __shfl_down_sync(0xffffffffu, s, o);
        if (lane == 0) g_qb[idx] = s + wk_b[a];
    } else {
        __shared__ float red[256];
        int t = threadIdx.x;
        float a0 = v_v[t], a1 = v_v[t + 256];
        red[t] = a0 * a0 + a1 * a1;
        __syncthreads();
        for (int o = 128; o > 0; o >>= 1) {
            if (t < o) red[t] += red[t + o];
            __syncthreads();
        }
        float inv = v_g[0] * rsqrtf(red[0]);
        g_vw[t]       = v_v[t] * inv;
        g_vw[t + 256] = v_v[t + 256] * inv;
    }
}

// ============================================================
// fused GEMM + tanh reduce -> e_mono  (mma.sync bf16, ldmatrix, cp.async)
// 512 CTAs x 256 thr; CTA = 128 rows x A=512 (4 ac chunks of 128)
// 32 flattened (ac,kc) wk chunks of [128n x 64k], double-buffered cp.async
// ============================================================
__global__ void __launch_bounds__(256, 1)
gemm_kernel(const float* __restrict__ key, const float* __restrict__ rv) {
    extern __shared__ char smem[];
    uint32_t sb = smem_u32(smem);
    __nv_bfloat16* key_s = (__nv_bfloat16*)smem;
    float2* qv_s  = (float2*)(smem + OFF_QV2);
    float*  e_red = (float*)(smem + OFF_ERED);

    int tid = threadIdx.x;
    int wid = tid >> 5, lane = tid & 31;
    int wr = wid >> 1, wc = wid & 1;        // warp row 0..3 (32 rows), col 0..1 (64 a)
    int gp = lane >> 2, tq = lane & 3;

    int b = blockIdx.x >> 5;
    size_t row0 = (size_t)blockIdx.x * 128;

    for (int i = tid; i < 512; i += 256)
        qv_s[i] = make_float2(g_qb[b * 512 + i], g_vw[i]);

    // stage key tile [128 x 512] fp32 -> bf16 (padded stride 520)
    const float* kg = key + row0 * 512;
    for (int e = tid * 4; e < 65536; e += 1024) {
        int r = e >> 9, c = e & 511;
        float4 v = *(const float4*)(kg + (size_t)r * 512 + c);
        uint32_t p0, p1;
        asm("cvt.rn.bf16x2.f32 %0, %1, %2;" : "=r"(p0) : "f"(v.y), "f"(v.x));
        asm("cvt.rn.bf16x2.f32 %0, %1, %2;" : "=r"(p1) : "f"(v.w), "f"(v.z));
        uint2 pk; pk.x = p0; pk.y = p1;
        *(uint2*)(key_s + r * KS_STRIDE + c) = pk;
    }

    // cp.async chunk copier: chunk i = (ac = i>>3, kc = i&7), 128n x 64k
    int cp_r = tid >> 1, cp_h = tid & 1;    // row 0..127, half 0..1 (32 cols)
    const __nv_bfloat16* wk_src0 = g_wk_bf16 + (size_t)cp_r * 512 + cp_h * 32;
    uint32_t wk_dst0 = sb + OFF_WKB + (uint32_t)(cp_r * WS_STRIDE + cp_h * 32) * 2u;

    #define COPY_CHUNK(i) do {                                              \
        int ac_ = (i) >> 3, kc_ = (i) & 7;                                  \
        const __nv_bfloat16* src = wk_src0 + (size_t)ac_ * 128 * 512 + kc_ * 64; \
        uint32_t dst = wk_dst0 + (uint32_t)((i) & 1) * 18432u;              \
        cp_async16(dst,       src);                                         \
        cp_async16(dst + 16,  src + 8);                                     \
        cp_async16(dst + 32,  src + 16);                                    \
        cp_async16(dst + 48,  src + 24);                                    \
        cp_commit();                                                        \
    } while (0)

    COPY_CHUNK(0);

    // ldmatrix lane addresses (byte offsets precomputed per lane)
    // A: row = wr*32 + mt*16 + (lane&15), col = kof + (lane>>4)*8
    uint32_t a_row = (uint32_t)(wr * 32 + (lane & 15));
    uint32_t a_cadd = (uint32_t)((lane >> 4) * 8);
    // B: row = wc*64 + j*16 + ((lane>>4)&1)*8 + (lane&7), col = ks*16 + ((lane>>3)&1)*8
    uint32_t b_row = (uint32_t)(wc * 64 + (((lane >> 4) & 1) * 8) + (lane & 7));
    uint32_t b_cadd = (uint32_t)(((lane >> 3) & 1) * 8);

    float acc[2][8][4];
    #pragma unroll
    for (int mt = 0; mt < 2; mt++)
        #pragma unroll
        for (int nt = 0; nt < 8; nt++)
            #pragma unroll
            for (int f = 0; f < 4; f++) acc[mt][nt][f] = 0.f;

    float erow[4] = {0.f, 0.f, 0.f, 0.f};

    __syncthreads();   // key_s + qv_s ready

    #pragma unroll 1
    for (int i = 0; i < 32; i++) {
        int kc = i & 7;
        uint32_t bbuf = sb + OFF_WKB + (uint32_t)(i & 1) * 18432u;
        cp_wait0();
        __syncthreads();
        if (i < 31) COPY_CHUNK(i + 1);

        #pragma unroll
        for (int ks = 0; ks < 4; ks++) {
            int kof = kc * 64 + ks * 16;
            uint32_t afr[2][4];
            #pragma unroll
            for (int mt = 0; mt < 2; mt++) {
                uint32_t aaddr = sb + ((a_row + mt * 16) * KS_STRIDE
                                       + kof + a_cadd) * 2u;
                ldsm_x4(aaddr, afr[mt][0], afr[mt][1], afr[mt][2], afr[mt][3]);
            }
            uint32_t bfr[8][2];
            #pragma unroll
            for (int j = 0; j < 4; j++) {
                uint32_t baddr = bbuf + ((b_row + j * 16) * WS_STRIDE
                                         + ks * 16 + b_cadd) * 2u;
                ldsm_x4(baddr, bfr[2 * j][0], bfr[2 * j][1],
                               bfr[2 * j + 1][0], bfr[2 * j + 1][1]);
            }
            #pragma unroll
            for (int mt = 0; mt < 2; mt++)
                #pragma unroll
                for (int nt = 0; nt < 8; nt++) {
                    asm volatile(
                        "mma.sync.aligned.m16n8k16.row.col.f32.bf16.bf16.f32 "
                        "{%0,%1,%2,%3}, {%4,%5,%6,%7}, {%8,%9}, {%0,%1,%2,%3};"
                        : "+f"(acc[mt][nt][0]), "+f"(acc[mt][nt][1]),
                          "+f"(acc[mt][nt][2]), "+f"(acc[mt][nt][3])
                        : "r"(afr[mt][0]), "r"(afr[mt][1]),
                          "r"(afr[mt][2]), "r"(afr[mt][3]),
                          "r"(bfr[nt][0]), "r"(bfr[nt][1]));
                }
        }

        if (kc == 7) {      // epilogue for this ac chunk
            int ac = i >> 3;
            #pragma unroll
            for (int mt = 0; mt < 2; mt++)
                #pragma unroll
                for (int nt = 0; nt < 8; nt++) {
                    int col = ac * 128 + wc * 64 + nt * 8 + tq * 2;
                    float2 qv0 = qv_s[col], qv1 = qv_s[col + 1];
                    erow[mt * 2 + 0] += tanh_fast(acc[mt][nt][0] + qv0.x) * qv0.y
                                      + tanh_fast(acc[mt][nt][1] + qv1.x) * qv1.y;
                    erow[mt * 2 + 1] += tanh_fast(acc[mt][nt][2] + qv0.x) * qv0.y
                                      + tanh_fast(acc[mt][nt][3] + qv1.x) * qv1.y;
                    acc[mt][nt][0] = 0.f; acc[mt][nt][1] = 0.f;
                    acc[mt][nt][2] = 0.f; acc[mt][nt][3] = 0.f;
                }
        }
    }

    // reduce the 4 lanes (tq) sharing each row
    #pragma unroll
    for (int i = 0; i < 4; i++) {
        erow[i] += __shfl_xor_sync(0xffffffffu, erow[i], 1);
        erow[i] += __shfl_xor_sync(0xffffffffu, erow[i], 2);
    }
    if (tq == 0) {
        int base = wc * 128 + wr * 32 + gp;
        e_red[base]      = erow[0];
        e_red[base + 8]  = erow[1];
        e_red[base + 16] = erow[2];
        e_red[base + 24] = erow[3];
    }
    __syncthreads();
    if (tid < 128)
        g_emono[row0 + tid] = e_red[tid] + e_red[128 + tid] + rv[0];
    #undef COPY_CHUNK
}

// ============================================================
// scan: aw[i] = p[i] * exp(1 + sum_{j<i} log(1-p[j])); grid 16 x 1024
// ============================================================
__global__ void __launch_bounds__(1024)
scan_kernel(const float* __restrict__ noise, float* __restrict__ out) {
    __shared__ float wsum[32];
    int b = blockIdx.x, t = threadIdx.x;
    float p[4], l[4], local = 0.f;
    #pragma unroll
    for (int i = 0; i < 4; i++) {
        int k = t * 4 + i;
        float e = g_emono[b * 4096 + k] + noise[b * 4096 + k];
        float pp = 1.f / (1.f + expf(-e));
        p[i] = pp;
        l[i] = logf(fmaxf(1.f - pp, 1e-10f));
        local += l[i];
    }
    float s = local;
    #pragma unroll
    for (int o = 1; o < 32; o <<= 1) {
        float v = __shfl_up_sync(0xffffffffu, s, o);
        if ((t & 31) >= o) s += v;
    }
    if ((t & 31) == 31) wsum[t >> 5] = s;
    __syncthreads();
    if (t < 32) {
        float v = wsum[t];
        #pragma unroll
        for (int o = 1; o < 32; o <<= 1) {
            float u = __shfl_up_sync(0xffffffffu, v, o);
            if (t >= o) v += u;
        }
        wsum[t] = v;
    }
    __syncthreads();
    float run = s - local;
    if (t >= 32) run += wsum[(t >> 5) - 1];
    #pragma unroll
    for (int i = 0; i < 4; i++) {
        int k = t * 4 + i;
        float aw = p[i] * expf(1.f + run);
        g_aw[b * 4096 + k] = aw;
        out[8192 + b * 4096 + k] = aw;
        run += l[i];
    }
}

// ============================================================
// cv partials: grid 512 = b*32 + split(128 rows); 2-way k-interleave, float4
// ============================================================
__global__ void __launch_bounds__(256)
cvpart_kernel(const float* __restrict__ value) {
    __shared__ float aw_s[128];
    int b = blockIdx.x >> 5, s = blockIdx.x & 31;
    int t = threadIdx.x;
    int rg = t >> 7, ct = t & 127;
    int k0 = s * 128;
    if (t < 128) aw_s[t] = g_aw[b * 4096 + k0 + t];
    __syncthreads();
    const float* vb = value + ((size_t)b * 4096 + k0) * 512;
    float4 acc = make_float4(0.f, 0.f, 0.f, 0.f);
    #pragma unroll 4
    for (int j = 0; j < 64; j++) {
        int k = j * 2 + rg;
        float w = aw_s[k];
        float4 v = *(const float4*)(vb + (size_t)k * 512 + ct * 4);
        acc.x += w * v.x; acc.y += w * v.y;
        acc.z += w * v.z; acc.w += w * v.w;
    }
    *(float4*)(g_cvpart + ((size_t)((b * 32 + s) * 2 + rg)) * 512 + ct * 4) = acc;
}

// reduce 64 partials -> cv : grid 32 x 256
__global__ void __launch_bounds__(256)
cvred_kernel(float* __restrict__ out) {
    int idx = blockIdx.x * 256 + threadIdx.x;   // 0..8191
    int b = idx >> 9, v = idx & 511;
    float s = 0.f;
    #pragma unroll
    for (int i = 0; i < 64; i++) s += g_cvpart[((size_t)(b * 64 + i)) * 512 + v];
    out[idx] = s;
}

// ============================================================
extern "C" void kernel_launch(void* const* d_in, const int* in_sizes, int n_in,
                              void* d_out, int out_size) {
    const float* key   = (const float*)d_in[0];
    const float* value = (const float*)d_in[1];
    const float* query = (const float*)d_in[2];
    const float* noise = (const float*)d_in[3];
    const float* wk_w  = (const float*)d_in[4];
    const float* wk_b  = (const float*)d_in[5];
    const float* wq_w  = (const float*)d_in[6];
    const float* v_v   = (const float*)d_in[7];
    const float* v_g   = (const float*)d_in[8];
    const float* r     = (const float*)d_in[9];
    float* out = (float*)d_out;

    cudaFuncSetAttribute(gemm_kernel,
        cudaFuncAttributeMaxDynamicSharedMemorySize, (int)SMEM_GEMM);

    prep_kernel<<<2049, 256>>>(wk_w, query, wq_w, wk_b, v_v, v_g);
    gemm_kernel<<<512, 256, SMEM_GEMM>>>(key, r);
    scan_kernel<<<16, 1024>>>(noise, out);
    cvpart_kernel<<<512, 256>>>(value);
    cvred_kernel<<<32, 256>>>(out);
}

// round 13
// speedup vs baseline: 1.1651x; 1.0687x over previous
#include <cuda_runtime.h>
#include <cuda_bf16.h>
#include <cstdint>

// MoChA: B=16, KMAX=4096, D=A=512. out[0:8192]=cv ; out[8192:73728]=aw
#define DINL __device__ __forceinline__
#define NROWS 65536
#define KS_STRIDE 520          // key smem row stride (bf16)
#define WS_STRIDE 72           // wk smem row stride (bf16)

__device__ __nv_bfloat16 g_wk_bf16[512 * 512];
__device__ float g_qb[16 * 512];
__device__ float g_vw[512];
__device__ float g_emono[NROWS];
__device__ float g_aw[NROWS];
__device__ float g_cvpart[16 * 128 * 512];  // 4 MB partials

// gemm smem (per CTA, 2 CTAs/SM):
// key_s [0, 66560) ; wk double buf [66560, +2*18432) ; qv ; e_red
#define OFF_WKB  66560u
#define OFF_QV2  103424u
#define OFF_ERED 107520u
#define SMEM_GEMM 108544u

DINL uint32_t smem_u32(const void* p) {
    uint32_t a;
    asm("{ .reg .u64 t; cvta.to.shared.u64 t, %1; cvt.u32.u64 %0, t; }"
        : "=r"(a) : "l"(p));
    return a;
}
DINL float tanh_fast(float x) {
    float y; asm("tanh.approx.f32 %0, %1;" : "=f"(y) : "f"(x)); return y;
}
DINL void cp_async16(uint32_t dst, const void* src) {
    asm volatile("cp.async.cg.shared.global [%0], [%1], 16;"
                 :: "r"(dst), "l"(src) : "memory");
}
DINL void cp_commit() { asm volatile("cp.async.commit_group;" ::: "memory"); }
DINL void cp_wait0()  { asm volatile("cp.async.wait_group 0;" ::: "memory"); }
DINL void ldsm_x4(uint32_t a, uint32_t& r0, uint32_t& r1, uint32_t& r2, uint32_t& r3) {
    asm volatile("ldmatrix.sync.aligned.m8n8.x4.shared.b16 {%0,%1,%2,%3}, [%4];"
                 : "=r"(r0), "=r"(r1), "=r"(r2), "=r"(r3) : "r"(a));
}

// ============================================================
// prep: wk fp32->bf16; qb = query@wq^T + wk_b; vw = weight-norm
// ============================================================
__global__ void prep_kernel(const float* __restrict__ wk_w,
                            const float* __restrict__ query,
                            const float* __restrict__ wq_w,
                            const float* __restrict__ wk_b,
                            const float* __restrict__ v_v,
                            const float* __restrict__ v_g) {
    int blk = blockIdx.x;
    if (blk < 1024) {
        int e = blk * 256 + threadIdx.x;
        g_wk_bf16[e] = __float2bfloat16(wk_w[e]);
    } else if (blk < 2048) {
        int wid = threadIdx.x >> 5, lane = threadIdx.x & 31;
        int idx = (blk - 1024) * 8 + wid;   // b*512+a
        int b = idx >> 9, a = idx & 511;
        const float* qrow = query + b * 512;
        const float* wrow = wq_w + (size_t)a * 512;
        float s = 0.f;
        #pragma unroll
        for (int i = 0; i < 16; i++) s += qrow[lane + i * 32] * wrow[lane + i * 32];
        #pragma unroll
        for (int o = 16; o > 0; o >>= 1) s += __shfl_down_sync(0xffffffffu, s, o);
        if (lane == 0) g_qb[idx] = s + wk_b[a];
    } else {
        __shared__ float red[256];
        int t = threadIdx.x;
        float a0 = v_v[t], a1 = v_v[t + 256];
        red[t] = a0 * a0 + a1 * a1;
        __syncthreads();
        for (int o = 128; o > 0; o >>= 1) {
            if (t < o) red[t] += red[t + o];
            __syncthreads();
        }
        float inv = v_g[0] * rsqrtf(red[0]);
        g_vw[t]       = v_v[t] * inv;
        g_vw[t + 256] = v_v[t + 256] * inv;
    }
}

// ============================================================
// fused GEMM + tanh reduce -> e_mono  (mma.sync bf16, ldmatrix, cp.async)
// 1024 CTAs x 256 thr, 2 CTAs/SM; CTA = 64 rows x A=512
// warps: 2(row, 32r) x 4(col, 32a); warp tile 32x32; mt=2, nt=4
// 32 flattened (ac,kc) wk chunks of [128a x 64k], double-buffered cp.async
// ============================================================
__global__ void __launch_bounds__(256, 2)
gemm_kernel(const float* __restrict__ key, const float* __restrict__ rv) {
    extern __shared__ char smem[];
    uint32_t sb = smem_u32(smem);
    __nv_bfloat16* key_s = (__nv_bfloat16*)smem;
    float2* qv_s  = (float2*)(smem + OFF_QV2);
    float*  e_red = (float*)(smem + OFF_ERED);

    int tid = threadIdx.x;
    int wid = tid >> 5, lane = tid & 31;
    int wr = wid >> 2, wc = wid & 3;        // warp row 0..1 (32 rows), col 0..3 (32 a)
    int gp = lane >> 2, tq = lane & 3;

    int b = blockIdx.x >> 6;                // 64 tiles of 64 rows per batch
    size_t row0 = (size_t)blockIdx.x * 64;

    for (int i = tid; i < 512; i += 256)
        qv_s[i] = make_float2(g_qb[b * 512 + i], g_vw[i]);

    // stage key tile [64 x 512] fp32 -> bf16 (padded stride 520)
    const float* kg = key + row0 * 512;
    for (int e = tid * 4; e < 32768; e += 1024) {
        int r = e >> 9, c = e & 511;
        float4 v = *(const float4*)(kg + (size_t)r * 512 + c);
        uint32_t p0, p1;
        asm("cvt.rn.bf16x2.f32 %0, %1, %2;" : "=r"(p0) : "f"(v.y), "f"(v.x));
        asm("cvt.rn.bf16x2.f32 %0, %1, %2;" : "=r"(p1) : "f"(v.w), "f"(v.z));
        uint2 pk; pk.x = p0; pk.y = p1;
        *(uint2*)(key_s + r * KS_STRIDE + c) = pk;
    }

    // cp.async chunk copier: chunk i = (ac = i>>3, kc = i&7), [128a x 64k]
    int cp_r = tid >> 1, cp_h = tid & 1;    // a-row 0..127, k-half 0..1
    const __nv_bfloat16* wk_src0 = g_wk_bf16 + (size_t)cp_r * 512 + cp_h * 32;
    uint32_t wk_dst0 = sb + OFF_WKB + (uint32_t)(cp_r * WS_STRIDE + cp_h * 32) * 2u;

    #define COPY_CHUNK(i) do {                                              \
        int ac_ = (i) >> 3, kc_ = (i) & 7;                                  \
        const __nv_bfloat16* src = wk_src0 + (size_t)ac_ * 128 * 512 + kc_ * 64; \
        uint32_t dst = wk_dst0 + (uint32_t)((i) & 1) * 18432u;              \
        cp_async16(dst,       src);                                         \
        cp_async16(dst + 16,  src + 8);                                     \
        cp_async16(dst + 32,  src + 16);                                    \
        cp_async16(dst + 48,  src + 24);                                    \
        cp_commit();                                                        \
    } while (0)

    COPY_CHUNK(0);

    // ldmatrix lane addresses
    // A: row = wr*32 + mt*16 + (lane&15), col = kof + (lane>>4)*8
    uint32_t a_row = (uint32_t)(wr * 32 + (lane & 15));
    uint32_t a_cadd = (uint32_t)((lane >> 4) * 8);
    // B: row = wc*32 + j*16 + ((lane>>4)&1)*8 + (lane&7), col = ks*16 + ((lane>>3)&1)*8
    uint32_t b_row = (uint32_t)(wc * 32 + (((lane >> 4) & 1) * 8) + (lane & 7));
    uint32_t b_cadd = (uint32_t)(((lane >> 3) & 1) * 8);

    float acc[2][4][4];
    #pragma unroll
    for (int mt = 0; mt < 2; mt++)
        #pragma unroll
        for (int nt = 0; nt < 4; nt++)
            #pragma unroll
            for (int f = 0; f < 4; f++) acc[mt][nt][f] = 0.f;

    float erow[4] = {0.f, 0.f, 0.f, 0.f};

    __syncthreads();   // key_s + qv_s ready

    #pragma unroll 1
    for (int i = 0; i < 32; i++) {
        int kc = i & 7;
        uint32_t bbuf = sb + OFF_WKB + (uint32_t)(i & 1) * 18432u;
        cp_wait0();
        __syncthreads();
        if (i < 31) COPY_CHUNK(i + 1);

        #pragma unroll
        for (int ks = 0; ks < 4; ks++) {
            int kof = kc * 64 + ks * 16;
            uint32_t afr[2][4];
            #pragma unroll
            for (int mt = 0; mt < 2; mt++) {
                uint32_t aaddr = sb + ((a_row + mt * 16) * KS_STRIDE
                                       + kof + a_cadd) * 2u;
                ldsm_x4(aaddr, afr[mt][0], afr[mt][1], afr[mt][2], afr[mt][3]);
            }
            uint32_t bfr[4][2];
            #pragma unroll
            for (int j = 0; j < 2; j++) {
                uint32_t baddr = bbuf + ((b_row + j * 16) * WS_STRIDE
                                         + ks * 16 + b_cadd) * 2u;
                ldsm_x4(baddr, bfr[2 * j][0], bfr[2 * j][1],
                               bfr[2 * j + 1][0], bfr[2 * j + 1][1]);
            }
            #pragma unroll
            for (int mt = 0; mt < 2; mt++)
                #pragma unroll
                for (int nt = 0; nt < 4; nt++) {
                    asm volatile(
                        "mma.sync.aligned.m16n8k16.row.col.f32.bf16.bf16.f32 "
                        "{%0,%1,%2,%3}, {%4,%5,%6,%7}, {%8,%9}, {%0,%1,%2,%3};"
                        : "+f"(acc[mt][nt][0]), "+f"(acc[mt][nt][1]),
                          "+f"(acc[mt][nt][2]), "+f"(acc[mt][nt][3])
                        : "r"(afr[mt][0]), "r"(afr[mt][1]),
                          "r"(afr[mt][2]), "r"(afr[mt][3]),
                          "r"(bfr[nt][0]), "r"(bfr[nt][1]));
                }
        }

        if (kc == 7) {      // epilogue for this ac chunk
            int ac = i >> 3;
            #pragma unroll
            for (int mt = 0; mt < 2; mt++)
                #pragma unroll
                for (int nt = 0; nt < 4; nt++) {
                    int col = ac * 128 + wc * 32 + nt * 8 + tq * 2;
                    float2 qv0 = qv_s[col], qv1 = qv_s[col + 1];
                    erow[mt * 2 + 0] += tanh_fast(acc[mt][nt][0] + qv0.x) * qv0.y
                                      + tanh_fast(acc[mt][nt][1] + qv1.x) * qv1.y;
                    erow[mt * 2 + 1] += tanh_fast(acc[mt][nt][2] + qv0.x) * qv0.y
                                      + tanh_fast(acc[mt][nt][3] + qv1.x) * qv1.y;
                    acc[mt][nt][0] = 0.f; acc[mt][nt][1] = 0.f;
                    acc[mt][nt][2] = 0.f; acc[mt][nt][3] = 0.f;
                }
        }
    }

    // reduce the 4 lanes (tq) sharing each row
    #pragma unroll
    for (int i = 0; i < 4; i++) {
        erow[i] += __shfl_xor_sync(0xffffffffu, erow[i], 1);
        erow[i] += __shfl_xor_sync(0xffffffffu, erow[i], 2);
    }
    if (tq == 0) {
        int base = wc * 64 + wr * 32 + gp;
        e_red[base]      = erow[0];
        e_red[base + 8]  = erow[1];
        e_red[base + 16] = erow[2];
        e_red[base + 24] = erow[3];
    }
    __syncthreads();
    if (tid < 64)
        g_emono[row0 + tid] = e_red[tid] + e_red[64 + tid]
                            + e_red[128 + tid] + e_red[192 + tid] + rv[0];
    #undef COPY_CHUNK
}

// ============================================================
// scan: aw[i] = p[i] * exp(1 + sum_{j<i} log(1-p[j])); grid 16 x 1024
// ============================================================
__global__ void __launch_bounds__(1024)
scan_kernel(const float* __restrict__ noise, float* __restrict__ out) {
    __shared__ float wsum[32];
    int b = blockIdx.x, t = threadIdx.x;
    float p[4], l[4], local = 0.f;
    #pragma unroll
    for (int i = 0; i < 4; i++) {
        int k = t * 4 + i;
        float e = g_emono[b * 4096 + k] + noise[b * 4096 + k];
        float pp = 1.f / (1.f + expf(-e));
        p[i] = pp;
        l[i] = logf(fmaxf(1.f - pp, 1e-10f));
        local += l[i];
    }
    float s = local;
    #pragma unroll
    for (int o = 1; o < 32; o <<= 1) {
        float v = __shfl_up_sync(0xffffffffu, s, o);
        if ((t & 31) >= o) s += v;
    }
    if ((t & 31) == 31) wsum[t >> 5] = s;
    __syncthreads();
    if (t < 32) {
        float v = wsum[t];
        #pragma unroll
        for (int o = 1; o < 32; o <<= 1) {
            float u = __shfl_up_sync(0xffffffffu, v, o);
            if (t >= o) v += u;
        }
        wsum[t] = v;
    }
    __syncthreads();
    float run = s - local;
    if (t >= 32) run += wsum[(t >> 5) - 1];
    #pragma unroll
    for (int i = 0; i < 4; i++) {
        int k = t * 4 + i;
        float aw = p[i] * expf(1.f + run);
        g_aw[b * 4096 + k] = aw;
        out[8192 + b * 4096 + k] = aw;
        run += l[i];
    }
}

// ============================================================
// cv partials: grid 1024 = b*64 + split(64 rows); 2-way k-interleave, float4
// ============================================================
__global__ void __launch_bounds__(256)
cvpart_kernel(const float* __restrict__ value) {
    __shared__ float aw_s[64];
    int b = blockIdx.x >> 6, s = blockIdx.x & 63;
    int t = threadIdx.x;
    int rg = t >> 7, ct = t & 127;
    int k0 = s * 64;
    if (t < 64) aw_s[t] = g_aw[b * 4096 + k0 + t];
    __syncthreads();
    const float* vb = value + ((size_t)b * 4096 + k0) * 512;
    float4 acc = make_float4(0.f, 0.f, 0.f, 0.f);
    #pragma unroll 4
    for (int j = 0; j < 32; j++) {
        int k = j * 2 + rg;
        float w = aw_s[k];
        float4 v = *(const float4*)(vb + (size_t)k * 512 + ct * 4);
        acc.x += w * v.x; acc.y += w * v.y;
        acc.z += w * v.z; acc.w += w * v.w;
    }
    *(float4*)(g_cvpart + ((size_t)((b * 64 + s) * 2 + rg)) * 512 + ct * 4) = acc;
}

// reduce 128 partials -> cv : grid 32 x 256
__global__ void __launch_bounds__(256)
cvred_kernel(float* __restrict__ out) {
    int idx = blockIdx.x * 256 + threadIdx.x;   // 0..8191
    int b = idx >> 9, v = idx & 511;
    float s = 0.f;
    #pragma unroll
    for (int i = 0; i < 128; i++) s += g_cvpart[((size_t)(b * 128 + i)) * 512 + v];
    out[idx] = s;
}

// ============================================================
extern "C" void kernel_launch(void* const* d_in, const int* in_sizes, int n_in,
                              void* d_out, int out_size) {
    const float* key   = (const float*)d_in[0];
    const float* value = (const float*)d_in[1];
    const float* query = (const float*)d_in[2];
    const float* noise = (const float*)d_in[3];
    const float* wk_w  = (const float*)d_in[4];
    const float* wk_b  = (const float*)d_in[5];
    const float* wq_w  = (const float*)d_in[6];
    const float* v_v   = (const float*)d_in[7];
    const float* v_g   = (const float*)d_in[8];
    const float* r     = (const float*)d_in[9];
    float* out = (float*)d_out;

    cudaFuncSetAttribute(gemm_kernel,
        cudaFuncAttributeMaxDynamicSharedMemorySize, (int)SMEM_GEMM);

    prep_kernel<<<2049, 256>>>(wk_w, query, wq_w, wk_b, v_v, v_g);
    gemm_kernel<<<1024, 256, SMEM_GEMM>>>(key, r);
    scan_kernel<<<16, 1024>>>(noise, out);
    cvpart_kernel<<<1024, 256>>>(value);
    cvred_kernel<<<32, 256>>>(out);
}

// round 14
// speedup vs baseline: 1.2118x; 1.0401x over previous
#include <cuda_runtime.h>
#include <cuda_fp16.h>
#include <cstdint>

// MoChA: B=16, KMAX=4096, D=A=512. out[0:8192]=cv ; out[8192:73728]=aw
#define DINL __device__ __forceinline__
#define NROWS 65536
#define KS_STRIDE 520          // key smem row stride (f16)
#define WS_STRIDE 72           // wk smem row stride (f16)

__device__ __half g_wk_f16[512 * 512];
__device__ float g_qb[16 * 512];
__device__ float g_vw[512];
__device__ float g_emono[NROWS];
__device__ float g_aw[NROWS];
__device__ float g_cvpart[16 * 128 * 512];  // 4 MB partials

// gemm smem (per CTA, 2 CTAs/SM):
// key_s [0, 66560) ; wk double buf [66560, +2*18432) ; qv ; e_red
#define OFF_WKB  66560u
#define OFF_QV2  103424u
#define OFF_ERED 107520u
#define SMEM_GEMM 108544u

DINL uint32_t smem_u32(const void* p) {
    uint32_t a;
    asm("{ .reg .u64 t; cvta.to.shared.u64 t, %1; cvt.u32.u64 %0, t; }"
        : "=r"(a) : "l"(p));
    return a;
}
DINL float tanh_fast(float x) {
    float y; asm("tanh.approx.f32 %0, %1;" : "=f"(y) : "f"(x)); return y;
}
DINL void cp_async16(uint32_t dst, const void* src) {
    asm volatile("cp.async.cg.shared.global [%0], [%1], 16;"
                 :: "r"(dst), "l"(src) : "memory");
}
DINL void cp_commit() { asm volatile("cp.async.commit_group;" ::: "memory"); }
DINL void cp_wait0()  { asm volatile("cp.async.wait_group 0;" ::: "memory"); }
DINL void ldsm_x4(uint32_t a, uint32_t& r0, uint32_t& r1, uint32_t& r2, uint32_t& r3) {
    asm volatile("ldmatrix.sync.aligned.m8n8.x4.shared.b16 {%0,%1,%2,%3}, [%4];"
                 : "=r"(r0), "=r"(r1), "=r"(r2), "=r"(r3) : "r"(a));
}

// ============================================================
// prep: wk fp32->fp16; qb = query@wq^T + wk_b; vw = weight-norm
// ============================================================
__global__ void prep_kernel(const float* __restrict__ wk_w,
                            const float* __restrict__ query,
                            const float* __restrict__ wq_w,
                            const float* __restrict__ wk_b,
                            const float* __restrict__ v_v,
                            const float* __restrict__ v_g) {
    int blk = blockIdx.x;
    if (blk < 1024) {
        int e = blk * 256 + threadIdx.x;
        g_wk_f16[e] = __float2half(wk_w[e]);
    } else if (blk < 2048) {
        int wid = threadIdx.x >> 5, lane = threadIdx.x & 31;
        int idx = (blk - 1024) * 8 + wid;   // b*512+a
        int b = idx >> 9, a = idx & 511;
        const float* qrow = query + b * 512;
        const float* wrow = wq_w + (size_t)a * 512;
        float s = 0.f;
        #pragma unroll
        for (int i = 0; i < 16; i++) s += qrow[lane + i * 32] * wrow[lane + i * 32];
        #pragma unroll
        for (int o = 16; o > 0; o >>= 1) s += __shfl_down_sync(0xffffffffu, s, o);
        if (lane == 0) g_qb[idx] = s + wk_b[a];
    } else {
        __shared__ float red[256];
        int t = threadIdx.x;
        float a0 = v_v[t], a1 = v_v[t + 256];
        red[t] = a0 * a0 + a1 * a1;
        __syncthreads();
        for (int o = 128; o > 0; o >>= 1) {
            if (t < o) red[t] += red[t + o];
            __syncthreads();
        }
        float inv = v_g[0] * rsqrtf(red[0]);
        g_vw[t]       = v_v[t] * inv;
        g_vw[t + 256] = v_v[t + 256] * inv;
    }
}

// ============================================================
// fused GEMM + tanh reduce -> e_mono  (mma.sync f16 w/ f16 accumulators)
// 1024 CTAs x 256 thr, 2 CTAs/SM; CTA = 64 rows x A=512
// warps: 2(row, 32r) x 4(col, 32a); warp tile 32x32; mt=2, nt=4
// 32 flattened (ac,kc) wk chunks of [128a x 64k], double-buffered cp.async
// ============================================================
__global__ void __launch_bounds__(256, 2)
gemm_kernel(const float* __restrict__ key, const float* __restrict__ rv) {
    extern __shared__ char smem[];
    uint32_t sb = smem_u32(smem);
    __half* key_s = (__half*)smem;
    float2* qv_s  = (float2*)(smem + OFF_QV2);
    float*  e_red = (float*)(smem + OFF_ERED);

    int tid = threadIdx.x;
    int wid = tid >> 5, lane = tid & 31;
    int wr = wid >> 2, wc = wid & 3;        // warp row 0..1 (32 rows), col 0..3 (32 a)
    int gp = lane >> 2, tq = lane & 3;

    int b = blockIdx.x >> 6;                // 64 tiles of 64 rows per batch
    size_t row0 = (size_t)blockIdx.x * 64;

    for (int i = tid; i < 512; i += 256)
        qv_s[i] = make_float2(g_qb[b * 512 + i], g_vw[i]);

    // stage key tile [64 x 512] fp32 -> fp16 (padded stride 520)
    const float* kg = key + row0 * 512;
    for (int e = tid * 4; e < 32768; e += 1024) {
        int r = e >> 9, c = e & 511;
        float4 v = *(const float4*)(kg + (size_t)r * 512 + c);
        uint32_t p0, p1;
        asm("cvt.rn.f16x2.f32 %0, %1, %2;" : "=r"(p0) : "f"(v.y), "f"(v.x));
        asm("cvt.rn.f16x2.f32 %0, %1, %2;" : "=r"(p1) : "f"(v.w), "f"(v.z));
        uint2 pk; pk.x = p0; pk.y = p1;
        *(uint2*)(key_s + r * KS_STRIDE + c) = pk;
    }

    // cp.async chunk copier: chunk i = (ac = i>>3, kc = i&7), [128a x 64k]
    int cp_r = tid >> 1, cp_h = tid & 1;    // a-row 0..127, k-half 0..1
    const __half* wk_src0 = g_wk_f16 + (size_t)cp_r * 512 + cp_h * 32;
    uint32_t wk_dst0 = sb + OFF_WKB + (uint32_t)(cp_r * WS_STRIDE + cp_h * 32) * 2u;

    #define COPY_CHUNK(i) do {                                              \
        int ac_ = (i) >> 3, kc_ = (i) & 7;                                  \
        const __half* src = wk_src0 + (size_t)ac_ * 128 * 512 + kc_ * 64;   \
        uint32_t dst = wk_dst0 + (uint32_t)((i) & 1) * 18432u;              \
        cp_async16(dst,       src);                                         \
        cp_async16(dst + 16,  src + 8);                                     \
        cp_async16(dst + 32,  src + 16);                                    \
        cp_async16(dst + 48,  src + 24);                                    \
        cp_commit();                                                        \
    } while (0)

    COPY_CHUNK(0);

    // ldmatrix lane addresses
    // A: row = wr*32 + mt*16 + (lane&15), col = kof + (lane>>4)*8
    uint32_t a_row = (uint32_t)(wr * 32 + (lane & 15));
    uint32_t a_cadd = (uint32_t)((lane >> 4) * 8);
    // B: row = wc*32 + j*16 + ((lane>>4)&1)*8 + (lane&7), col = ks*16 + ((lane>>3)&1)*8
    uint32_t b_row = (uint32_t)(wc * 32 + (((lane >> 4) & 1) * 8) + (lane & 7));
    uint32_t b_cadd = (uint32_t)(((lane >> 3) & 1) * 8);

    // f16x2 accumulators: acc[mt][nt][0] = rows gp, cols (tq*2, tq*2+1)
    //                     acc[mt][nt][1] = rows gp+8, same cols
    uint32_t acc[2][4][2];
    #pragma unroll
    for (int mt = 0; mt < 2; mt++)
        #pragma unroll
        for (int nt = 0; nt < 4; nt++) { acc[mt][nt][0] = 0u; acc[mt][nt][1] = 0u; }

    float erow[4] = {0.f, 0.f, 0.f, 0.f};

    __syncthreads();   // key_s + qv_s ready

    #pragma unroll 1
    for (int i = 0; i < 32; i++) {
        int kc = i & 7;
        uint32_t bbuf = sb + OFF_WKB + (uint32_t)(i & 1) * 18432u;
        cp_wait0();
        __syncthreads();
        if (i < 31) COPY_CHUNK(i + 1);

        #pragma unroll
        for (int ks = 0; ks < 4; ks++) {
            int kof = kc * 64 + ks * 16;
            uint32_t afr[2][4];
            #pragma unroll
            for (int mt = 0; mt < 2; mt++) {
                uint32_t aaddr = sb + ((a_row + mt * 16) * KS_STRIDE
                                       + kof + a_cadd) * 2u;
                ldsm_x4(aaddr, afr[mt][0], afr[mt][1], afr[mt][2], afr[mt][3]);
            }
            uint32_t bfr[4][2];
            #pragma unroll
            for (int j = 0; j < 2; j++) {
                uint32_t baddr = bbuf + ((b_row + j * 16) * WS_STRIDE
                                         + ks * 16 + b_cadd) * 2u;
                ldsm_x4(baddr, bfr[2 * j][0], bfr[2 * j][1],
                               bfr[2 * j + 1][0], bfr[2 * j + 1][1]);
            }
            #pragma unroll
            for (int mt = 0; mt < 2; mt++)
                #pragma unroll
                for (int nt = 0; nt < 4; nt++) {
                    asm volatile(
                        "mma.sync.aligned.m16n8k16.row.col.f16.f16.f16.f16 "
                        "{%0,%1}, {%2,%3,%4,%5}, {%6,%7}, {%0,%1};"
                        : "+r"(acc[mt][nt][0]), "+r"(acc[mt][nt][1])
                        : "r"(afr[mt][0]), "r"(afr[mt][1]),
                          "r"(afr[mt][2]), "r"(afr[mt][3]),
                          "r"(bfr[nt][0]), "r"(bfr[nt][1]));
                }
        }

        if (kc == 7) {      // epilogue for this ac chunk
            int ac = i >> 3;
            #pragma unroll
            for (int mt = 0; mt < 2; mt++)
                #pragma unroll
                for (int nt = 0; nt < 4; nt++) {
                    int col = ac * 128 + wc * 32 + nt * 8 + tq * 2;
                    float2 qv0 = qv_s[col], qv1 = qv_s[col + 1];
                    float2 f0 = __half22float2(*(__half2*)&acc[mt][nt][0]);
                    float2 f1 = __half22float2(*(__half2*)&acc[mt][nt][1]);
                    erow[mt * 2 + 0] += tanh_fast(f0.x + qv0.x) * qv0.y
                                      + tanh_fast(f0.y + qv1.x) * qv1.y;
                    erow[mt * 2 + 1] += tanh_fast(f1.x + qv0.x) * qv0.y
                                      + tanh_fast(f1.y + qv1.x) * qv1.y;
                    acc[mt][nt][0] = 0u; acc[mt][nt][1] = 0u;
                }
        }
    }

    // reduce the 4 lanes (tq) sharing each row
    #pragma unroll
    for (int i = 0; i < 4; i++) {
        erow[i] += __shfl_xor_sync(0xffffffffu, erow[i], 1);
        erow[i] += __shfl_xor_sync(0xffffffffu, erow[i], 2);
    }
    if (tq == 0) {
        int base = wc * 64 + wr * 32 + gp;
        e_red[base]      = erow[0];
        e_red[base + 8]  = erow[1];
        e_red[base + 16] = erow[2];
        e_red[base + 24] = erow[3];
    }
    __syncthreads();
    if (tid < 64)
        g_emono[row0 + tid] = e_red[tid] + e_red[64 + tid]
                            + e_red[128 + tid] + e_red[192 + tid] + rv[0];
    #undef COPY_CHUNK
}

// ============================================================
// scan: aw[i] = p[i] * exp(1 + sum_{j<i} log(1-p[j])); grid 16 x 1024
// ============================================================
__global__ void __launch_bounds__(1024)
scan_kernel(const float* __restrict__ noise, float* __restrict__ out) {
    __shared__ float wsum[32];
    int b = blockIdx.x, t = threadIdx.x;
    float p[4], l[4], local = 0.f;
    #pragma unroll
    for (int i = 0; i < 4; i++) {
        int k = t * 4 + i;
        float e = g_emono[b * 4096 + k] + noise[b * 4096 + k];
        float pp = 1.f / (1.f + expf(-e));
        p[i] = pp;
        l[i] = logf(fmaxf(1.f - pp, 1e-10f));
        local += l[i];
    }
    float s = local;
    #pragma unroll
    for (int o = 1; o < 32; o <<= 1) {
        float v = __shfl_up_sync(0xffffffffu, s, o);
        if ((t & 31) >= o) s += v;
    }
    if ((t & 31) == 31) wsum[t >> 5] = s;
    __syncthreads();
    if (t < 32) {
        float v = wsum[t];
        #pragma unroll
        for (int o = 1; o < 32; o <<= 1) {
            float u = __shfl_up_sync(0xffffffffu, v, o);
            if (t >= o) v += u;
        }
        wsum[t] = v;
    }
    __syncthreads();
    float run = s - local;
    if (t >= 32) run += wsum[(t >> 5) - 1];
    #pragma unroll
    for (int i = 0; i < 4; i++) {
        int k = t * 4 + i;
        float aw = p[i] * expf(1.f + run);
        g_aw[b * 4096 + k] = aw;
        out[8192 + b * 4096 + k] = aw;
        run += l[i];
    }
}

// ============================================================
// cv partials: grid 1024 = b*64 + split(64 rows); 2-way k-interleave, float4
// ============================================================
__global__ void __launch_bounds__(256)
cvpart_kernel(const float* __restrict__ value) {
    __shared__ float aw_s[64];
    int b = blockIdx.x >> 6, s = blockIdx.x & 63;
    int t = threadIdx.x;
    int rg = t >> 7, ct = t & 127;
    int k0 = s * 64;
    if (t < 64) aw_s[t] = g_aw[b * 4096 + k0 + t];
    __syncthreads();
    const float* vb = value + ((size_t)b * 4096 + k0) * 512;
    float4 acc = make_float4(0.f, 0.f, 0.f, 0.f);
    #pragma unroll 4
    for (int j = 0; j < 32; j++) {
        int k = j * 2 + rg;
        float w = aw_s[k];
        float4 v = *(const float4*)(vb + (size_t)k * 512 + ct * 4);
        acc.x += w * v.x; acc.y += w * v.y;
        acc.z += w * v.z; acc.w += w * v.w;
    }
    *(float4*)(g_cvpart + ((size_t)((b * 64 + s) * 2 + rg)) * 512 + ct * 4) = acc;
}

// reduce 128 partials -> cv : grid 32 x 256
__global__ void __launch_bounds__(256)
cvred_kernel(float* __restrict__ out) {
    int idx = blockIdx.x * 256 + threadIdx.x;   // 0..8191
    int b = idx >> 9, v = idx & 511;
    float s = 0.f;
    #pragma unroll
    for (int i = 0; i < 128; i++) s += g_cvpart[((size_t)(b * 128 + i)) * 512 + v];
    out[idx] = s;
}

// ============================================================
extern "C" void kernel_launch(void* const* d_in, const int* in_sizes, int n_in,
                              void* d_out, int out_size) {
    const float* key   = (const float*)d_in[0];
    const float* value = (const float*)d_in[1];
    const float* query = (const float*)d_in[2];
    const float* noise = (const float*)d_in[3];
    const float* wk_w  = (const float*)d_in[4];
    const float* wk_b  = (const float*)d_in[5];
    const float* wq_w  = (const float*)d_in[6];
    const float* v_v   = (const float*)d_in[7];
    const float* v_g   = (const float*)d_in[8];
    const float* r     = (const float*)d_in[9];
    float* out = (float*)d_out;

    cudaFuncSetAttribute(gemm_kernel,
        cudaFuncAttributeMaxDynamicSharedMemorySize, (int)SMEM_GEMM);

    prep_kernel<<<2049, 256>>>(wk_w, query, wq_w, wk_b, v_v, v_g);
    gemm_kernel<<<1024, 256, SMEM_GEMM>>>(key, r);
    scan_kernel<<<16, 1024>>>(noise, out);
    cvpart_kernel<<<1024, 256>>>(value);
    cvred_kernel<<<32, 256>>>(out);
}